// round 3
// baseline (speedup 1.0000x reference)
#include <cuda_runtime.h>
#include <math.h>

#define T_DIM 512
#define B_DIM 128
#define D_DIM 1024
#define H_DIM 1024

// Scratch: x_gates [T][4][B][H] = 1 GiB, LSTM state (h double-buffered, c)
__device__ float g_xg[(size_t)T_DIM * 4 * B_DIM * H_DIM];
__device__ float g_h[2][B_DIM * H_DIM];
__device__ float g_c[B_DIM * H_DIM];

// ---------------------------------------------------------------------------
// init: zero h (both buffers) and c
// ---------------------------------------------------------------------------
__global__ void init_state_kernel() {
    int i = blockIdx.x * blockDim.x + threadIdx.x;
    if (i < B_DIM * H_DIM) {
        g_h[0][i] = 0.0f;
        g_h[1][i] = 0.0f;
        g_c[i]    = 0.0f;
    }
}

// ---------------------------------------------------------------------------
// GEMM1: x_gates[t][g][b][h] = sum_d x[b][t][d] * Wx[g][d][h]
// A = x viewed as [M=65536 (m=b*512+t), K=1024], B = Wx[g] as [K=1024, H=1024]
// 128x128x16 tile, 256 threads, 8x8 micro-tile per thread.
// ---------------------------------------------------------------------------
__global__ __launch_bounds__(256) void gemm_xgates_kernel(
    const float* __restrict__ X, const float* __restrict__ Wx)
{
    __shared__ float As[16][128];   // [k][m] (transposed on load)
    __shared__ float Bs[16][128];   // [k][n]

    const int tid = threadIdx.x;
    const int bn  = blockIdx.x * 128;          // over N = 4096 (g*1024 + h)
    const int bm  = blockIdx.y * 128;          // over M = 65536
    const int g   = bn >> 10;
    const int h0  = bn & 1023;
    const float* Bmat = Wx + (size_t)g * D_DIM * H_DIM;   // [D][H] row-major

    const int tx = tid & 15;    // 0..15  (n)
    const int ty = tid >> 4;    // 0..15  (m)

    float acc[8][8];
#pragma unroll
    for (int i = 0; i < 8; ++i)
#pragma unroll
        for (int j = 0; j < 8; ++j) acc[i][j] = 0.0f;

    for (int k0 = 0; k0 < D_DIM; k0 += 16) {
        // Load A tile (128 m x 16 k), transpose into As[k][m]
#pragma unroll
        for (int l = 0; l < 2; ++l) {
            int idx = tid + l * 256;          // 0..511
            int row = idx >> 2;               // 0..127
            int kq  = (idx & 3) * 4;          // 0,4,8,12
            float4 v = *(const float4*)&X[(size_t)(bm + row) * D_DIM + k0 + kq];
            As[kq + 0][row] = v.x;
            As[kq + 1][row] = v.y;
            As[kq + 2][row] = v.z;
            As[kq + 3][row] = v.w;
        }
        // Load B tile (16 k x 128 n)
#pragma unroll
        for (int l = 0; l < 2; ++l) {
            int idx = tid + l * 256;
            int row = idx >> 5;               // 0..15
            int nq  = (idx & 31) * 4;         // 0..124
            *(float4*)&Bs[row][nq] =
                *(const float4*)&Bmat[(size_t)(k0 + row) * H_DIM + h0 + nq];
        }
        __syncthreads();

#pragma unroll
        for (int k = 0; k < 16; ++k) {
            float fa[8], fb[8];
            *(float4*)&fa[0] = *(const float4*)&As[k][ty * 4];
            *(float4*)&fa[4] = *(const float4*)&As[k][ty * 4 + 64];
            *(float4*)&fb[0] = *(const float4*)&Bs[k][tx * 4];
            *(float4*)&fb[4] = *(const float4*)&Bs[k][tx * 4 + 64];
#pragma unroll
            for (int i = 0; i < 8; ++i)
#pragma unroll
                for (int j = 0; j < 8; ++j)
                    acc[i][j] += fa[i] * fb[j];
        }
        __syncthreads();
    }

    // Write to g_xg[t][g][b][h]; m = b*512 + t
#pragma unroll
    for (int i = 0; i < 8; ++i) {
        int mo = (i < 4) ? (ty * 4 + i) : (64 + ty * 4 + (i - 4));
        int m  = bm + mo;
        int b  = m >> 9;
        int t  = m & 511;
        float* orow = g_xg + (size_t)((t * 4 + g) * B_DIM + b) * H_DIM + h0;
#pragma unroll
        for (int jj = 0; jj < 2; ++jj) {
            int n = (jj == 0) ? (tx * 4) : (64 + tx * 4);
            float4 v;
            v.x = acc[i][jj * 4 + 0];
            v.y = acc[i][jj * 4 + 1];
            v.z = acc[i][jj * 4 + 2];
            v.w = acc[i][jj * 4 + 3];
            *(float4*)&orow[n] = v;
        }
    }
}

// ---------------------------------------------------------------------------
// Per-step fused LSTM cell:
//   gates[g][b][h] = xg[t][g][b][h] + sum_j h_prev[b][j]*Wh[g][j][h] + bias[g][h]
//   c = sigm(f)*c + sigm(i)*tanh(u); h = sigm(o)*tanh(c)
// Block computes [64 b x 16 h] x 4 gates, K = 1024 tiled by 32.
// 256 threads: tx = h lane (16), bt = b lane (16), 4 b's per thread (strided).
// h is double-buffered across steps (read t%2, write (t+1)%2); c is
// owner-computes (same thread reads+writes its (b,h)) so no hazard.
// ---------------------------------------------------------------------------
__device__ __forceinline__ float sigmoidf_(float x) {
    return 1.0f / (1.0f + expf(-x));
}

__global__ __launch_bounds__(256) void lstm_step_kernel(
    const float* __restrict__ Wh, const float* __restrict__ bias, int t)
{
    __shared__ float Hs[32][64];        // [k][b]
    __shared__ float Ws[4][32][16];     // [g][k][h]

    const float* __restrict__ hin  = g_h[t & 1];
    float* __restrict__       hout = g_h[(t + 1) & 1];

    const int tid = threadIdx.x;
    const int tx  = tid & 15;           // h within tile
    const int bt  = tid >> 4;           // 0..15
    const int h0  = blockIdx.x * 16;    // 64 tiles over H
    const int b0  = blockIdx.y * 64;    // 2 tiles over B

    float acc[4][4];
#pragma unroll
    for (int i = 0; i < 4; ++i)
#pragma unroll
        for (int g = 0; g < 4; ++g) acc[i][g] = 0.0f;

    for (int k0 = 0; k0 < H_DIM; k0 += 32) {
        // Load h_prev tile [64 b x 32 k], transpose into Hs[k][b]
#pragma unroll
        for (int l = 0; l < 2; ++l) {
            int idx = tid + l * 256;          // 0..511
            int bb  = idx >> 3;               // 0..63
            int kq  = (idx & 7) * 4;          // 0..28
            float4 v = *(const float4*)&hin[(b0 + bb) * H_DIM + k0 + kq];
            Hs[kq + 0][bb] = v.x;
            Hs[kq + 1][bb] = v.y;
            Hs[kq + 2][bb] = v.z;
            Hs[kq + 3][bb] = v.w;
        }
        // Load Wh tile [4 g x 32 k x 16 h]
#pragma unroll
        for (int l = 0; l < 2; ++l) {
            int idx = tid + l * 256;
            int row = idx >> 2;               // 0..127 = g*32 + kk
            int hq  = (idx & 3) * 4;          // 0..12
            int g   = row >> 5;
            int kk  = row & 31;
            *(float4*)&Ws[g][kk][hq] =
                *(const float4*)&Wh[(size_t)(g * H_DIM + k0 + kk) * H_DIM + h0 + hq];
        }
        __syncthreads();

#pragma unroll
        for (int k = 0; k < 32; ++k) {
            float wf[4], hf[4];
#pragma unroll
            for (int g = 0; g < 4; ++g) wf[g] = Ws[g][k][tx];
#pragma unroll
            for (int i = 0; i < 4; ++i) hf[i] = Hs[k][bt + i * 16];
#pragma unroll
            for (int i = 0; i < 4; ++i)
#pragma unroll
                for (int g = 0; g < 4; ++g)
                    acc[i][g] += hf[i] * wf[g];
        }
        __syncthreads();
    }

    const int h = h0 + tx;
#pragma unroll
    for (int i = 0; i < 4; ++i) {
        int b = b0 + bt + i * 16;
        size_t base = (size_t)(t * 4) * B_DIM * H_DIM + (size_t)b * H_DIM + h;
        float gi = acc[i][0] + g_xg[base + 0 * (size_t)B_DIM * H_DIM] + bias[0 * H_DIM + h];
        float gf = acc[i][1] + g_xg[base + 1 * (size_t)B_DIM * H_DIM] + bias[1 * H_DIM + h];
        float go = acc[i][2] + g_xg[base + 2 * (size_t)B_DIM * H_DIM] + bias[2 * H_DIM + h];
        float gu = acc[i][3] + g_xg[base + 3 * (size_t)B_DIM * H_DIM] + bias[3 * H_DIM + h];

        float iv = sigmoidf_(gi);
        float fv = sigmoidf_(gf);
        float ov = sigmoidf_(go);
        float uv = tanhf(gu);

        int sidx = b * H_DIM + h;
        float c  = fv * g_c[sidx] + iv * uv;
        g_c[sidx]  = c;
        hout[sidx] = ov * tanhf(c);
    }
}

// ---------------------------------------------------------------------------
// copy final h (buffer 0 after 512 steps) to d_out
// ---------------------------------------------------------------------------
__global__ void copy_out_kernel(float* __restrict__ out) {
    int i = blockIdx.x * blockDim.x + threadIdx.x;
    if (i < B_DIM * H_DIM) out[i] = g_h[0][i];
}

// ---------------------------------------------------------------------------
extern "C" void kernel_launch(void* const* d_in, const int* in_sizes, int n_in,
                              void* d_out, int out_size)
{
    const float* x    = (const float*)d_in[0];
    // d_in[1] = adjacency, unused by the reference forward
    const float* Wx   = (const float*)d_in[2];
    const float* Wh   = (const float*)d_in[3];
    const float* bias = (const float*)d_in[4];
    float* out = (float*)d_out;

    init_state_kernel<<<(B_DIM * H_DIM + 255) / 256, 256>>>();

    // Big input-projection GEMM: [65536 x 1024] @ [1024 x 4096]
    gemm_xgates_kernel<<<dim3(4096 / 128, 65536 / 128), 256>>>(x, Wx);

    // Sequential scan over T
    for (int t = 0; t < T_DIM; ++t) {
        lstm_step_kernel<<<dim3(H_DIM / 16, B_DIM / 64), 256>>>(Wh, bias, t);
    }

    copy_out_kernel<<<(B_DIM * H_DIM + 255) / 256, 256>>>(out);
}

// round 4
// speedup vs baseline: 1.6346x; 1.6346x over previous
#include <cuda_runtime.h>
#include <cuda_bf16.h>
#include <math.h>
#include <stdint.h>

#define T_DIM 512
#define B_DIM 128
#define D_DIM 1024
#define H_DIM 1024

// ---------------------------------------------------------------------------
// Global scratch
// ---------------------------------------------------------------------------
__device__ float g_xg[(size_t)T_DIM * 4 * B_DIM * H_DIM];   // [t][g][b][h]
__device__ float g_h[2][B_DIM * H_DIM];                     // fp32 h (for output)
__device__ float g_c[B_DIM * H_DIM];

// bf16 split state + weights
__device__ __nv_bfloat16 g_h_hi[2][B_DIM * H_DIM];
__device__ __nv_bfloat16 g_h_lo[2][B_DIM * H_DIM];
// Wh pre-split AND transposed to [g][h][k] (k contiguous)
__device__ __nv_bfloat16 g_wh_hi[(size_t)4 * H_DIM * H_DIM];
__device__ __nv_bfloat16 g_wh_lo[(size_t)4 * H_DIM * H_DIM];

// ---------------------------------------------------------------------------
// init: zero h (both buffers, fp32 + bf16 splits) and c
// ---------------------------------------------------------------------------
__global__ void init_state_kernel() {
    int i = blockIdx.x * blockDim.x + threadIdx.x;
    if (i < B_DIM * H_DIM) {
        g_h[0][i] = 0.0f;
        g_h[1][i] = 0.0f;
        g_c[i]    = 0.0f;
        __nv_bfloat16 z = __float2bfloat16(0.0f);
        g_h_hi[0][i] = z; g_h_hi[1][i] = z;
        g_h_lo[0][i] = z; g_h_lo[1][i] = z;
    }
}

// ---------------------------------------------------------------------------
// Split Wh (fp32 [g][k][h]) into bf16 hi/lo, transposed to [g][h][k].
// One-time cost per launch; uncoalesced writes are fine here.
// ---------------------------------------------------------------------------
__global__ void split_wh_kernel(const float* __restrict__ Wh) {
    size_t i = (size_t)blockIdx.x * blockDim.x + threadIdx.x;
    if (i < (size_t)4 * H_DIM * H_DIM) {
        size_t g = i >> 20;            // /(1024*1024)
        size_t r = i & ((1u << 20) - 1);
        size_t k = r >> 10;
        size_t h = r & 1023;
        float w = Wh[i];
        __nv_bfloat16 hi = __float2bfloat16(w);
        float lo = w - __bfloat162float(hi);
        size_t o = ((g << 10) + h) * H_DIM + k;   // [g][h][k]
        g_wh_hi[o] = hi;
        g_wh_lo[o] = __float2bfloat16(lo);
    }
}

// ---------------------------------------------------------------------------
// GEMM1 (unchanged fp32 SIMT): x_gates[t][g][b][h] = sum_d x[b][t][d]*Wx[g][d][h]
// ---------------------------------------------------------------------------
__global__ __launch_bounds__(256) void gemm_xgates_kernel(
    const float* __restrict__ X, const float* __restrict__ Wx)
{
    __shared__ float As[16][128];
    __shared__ float Bs[16][128];

    const int tid = threadIdx.x;
    const int bn  = blockIdx.x * 128;
    const int bm  = blockIdx.y * 128;
    const int g   = bn >> 10;
    const int h0  = bn & 1023;
    const float* Bmat = Wx + (size_t)g * D_DIM * H_DIM;

    const int tx = tid & 15;
    const int ty = tid >> 4;

    float acc[8][8];
#pragma unroll
    for (int i = 0; i < 8; ++i)
#pragma unroll
        for (int j = 0; j < 8; ++j) acc[i][j] = 0.0f;

    for (int k0 = 0; k0 < D_DIM; k0 += 16) {
#pragma unroll
        for (int l = 0; l < 2; ++l) {
            int idx = tid + l * 256;
            int row = idx >> 2;
            int kq  = (idx & 3) * 4;
            float4 v = *(const float4*)&X[(size_t)(bm + row) * D_DIM + k0 + kq];
            As[kq + 0][row] = v.x;
            As[kq + 1][row] = v.y;
            As[kq + 2][row] = v.z;
            As[kq + 3][row] = v.w;
        }
#pragma unroll
        for (int l = 0; l < 2; ++l) {
            int idx = tid + l * 256;
            int row = idx >> 5;
            int nq  = (idx & 31) * 4;
            *(float4*)&Bs[row][nq] =
                *(const float4*)&Bmat[(size_t)(k0 + row) * H_DIM + h0 + nq];
        }
        __syncthreads();

#pragma unroll
        for (int k = 0; k < 16; ++k) {
            float fa[8], fb[8];
            *(float4*)&fa[0] = *(const float4*)&As[k][ty * 4];
            *(float4*)&fa[4] = *(const float4*)&As[k][ty * 4 + 64];
            *(float4*)&fb[0] = *(const float4*)&Bs[k][tx * 4];
            *(float4*)&fb[4] = *(const float4*)&Bs[k][tx * 4 + 64];
#pragma unroll
            for (int i = 0; i < 8; ++i)
#pragma unroll
                for (int j = 0; j < 8; ++j)
                    acc[i][j] += fa[i] * fb[j];
        }
        __syncthreads();
    }

#pragma unroll
    for (int i = 0; i < 8; ++i) {
        int mo = (i < 4) ? (ty * 4 + i) : (64 + ty * 4 + (i - 4));
        int m  = bm + mo;
        int b  = m >> 9;
        int t  = m & 511;
        float* orow = g_xg + (size_t)((t * 4 + g) * B_DIM + b) * H_DIM + h0;
#pragma unroll
        for (int jj = 0; jj < 2; ++jj) {
            int n = (jj == 0) ? (tx * 4) : (64 + tx * 4);
            float4 v;
            v.x = acc[i][jj * 4 + 0];
            v.y = acc[i][jj * 4 + 1];
            v.z = acc[i][jj * 4 + 2];
            v.w = acc[i][jj * 4 + 3];
            *(float4*)&orow[n] = v;
        }
    }
}

// ---------------------------------------------------------------------------
// mma.sync-based LSTM step.
// Block: 32 b x (4 gates x 16 h). Grid (64 h-groups, 4 b-groups) = 256 blocks.
// 8 warps = 2 m-warps x 4 gates; each warp: 16b x 16h of one gate.
// Split-bf16: gates += Ah*Bh + Ah*Bl + Al*Bh  (fp32 accumulate).
// ---------------------------------------------------------------------------
#define KC  64          // k-chunk in elements (halves)
#define KCW 32          // k-chunk in 32-bit words
#define APW 33          // A row pitch in words (padded)
#define BPW 33          // B row pitch in words (padded)

__device__ __forceinline__ float sigmoidf_(float x) {
    return 1.0f / (1.0f + expf(-x));
}

#define MMA16816(C, A0, A1, A2, A3, B0, B1)                                  \
    asm volatile(                                                            \
        "mma.sync.aligned.m16n8k16.row.col.f32.bf16.bf16.f32 "               \
        "{%0,%1,%2,%3}, {%4,%5,%6,%7}, {%8,%9}, {%0,%1,%2,%3};"              \
        : "+f"(C[0]), "+f"(C[1]), "+f"(C[2]), "+f"(C[3])                     \
        : "r"(A0), "r"(A1), "r"(A2), "r"(A3), "r"(B0), "r"(B1))

__global__ __launch_bounds__(256) void lstm_step_mma_kernel(
    const float* __restrict__ bias, int t)
{
    __shared__ uint32_t AsH[32 * APW];       // h_hi  [b][kw]
    __shared__ uint32_t AsL[32 * APW];       // h_lo
    __shared__ uint32_t BsH[64 * BPW];       // wh_hi [col][kw], col = g*16+hl
    __shared__ uint32_t BsL[64 * BPW];
    __shared__ float    smg[4][32][17];      // gates [g][b][h]

    const int tid = threadIdx.x;
    const int wid = tid >> 5;
    const int l   = tid & 31;
    const int mw  = wid & 1;          // m-warp (16 b rows)
    const int gw  = wid >> 1;         // gate 0..3
    const int h0  = blockIdx.x * 16;  // 64 groups over H
    const int b0  = blockIdx.y * 32;  // 4 groups over B

    const uint32_t* __restrict__ hHiU = (const uint32_t*)g_h_hi[t & 1];
    const uint32_t* __restrict__ hLoU = (const uint32_t*)g_h_lo[t & 1];
    const uint32_t* __restrict__ wHiU = (const uint32_t*)g_wh_hi;
    const uint32_t* __restrict__ wLoU = (const uint32_t*)g_wh_lo;

    float c0[4] = {0.f, 0.f, 0.f, 0.f};   // n-tile 0 (h 0..7)
    float c1[4] = {0.f, 0.f, 0.f, 0.f};   // n-tile 1 (h 8..15)

    const int gq = l >> 2;   // 0..7
    const int tq = l & 3;    // 0..3

    for (int k0 = 0; k0 < H_DIM; k0 += KC) {
        __syncthreads();
        const int kw0 = k0 >> 1;   // word offset into k
        // --- load A: 32 rows x 32 words, both splits (coalesced 128B) ---
#pragma unroll
        for (int it = 0; it < 4; ++it) {
            int i  = tid + it * 256;          // 0..1023
            int b  = i >> 5;
            int kw = i & 31;
            uint32_t ga = (uint32_t)(b0 + b) * (H_DIM / 2) + kw0 + kw;
            AsH[b * APW + kw] = hHiU[ga];
            AsL[b * APW + kw] = hLoU[ga];
        }
        // --- load B: 64 cols x 32 words, both splits (coalesced 128B) ---
#pragma unroll
        for (int it = 0; it < 8; ++it) {
            int i   = tid + it * 256;         // 0..2047
            int col = i >> 5;                 // 0..63 = gg*16 + hl
            int kw  = i & 31;
            int gg  = col >> 4;
            int hl  = col & 15;
            uint32_t ga = ((uint32_t)(gg << 10) + h0 + hl) * (H_DIM / 2) + kw0 + kw;
            BsH[col * BPW + kw] = wHiU[ga];
            BsL[col * BPW + kw] = wLoU[ga];
        }
        __syncthreads();

#pragma unroll
        for (int kk = 0; kk < KC; kk += 16) {
            const int kw = (kk >> 1) + tq;
            const int r0 = (mw * 16 + gq) * APW;
            const int r1 = (mw * 16 + gq + 8) * APW;
            uint32_t ah0 = AsH[r0 + kw];
            uint32_t ah1 = AsH[r1 + kw];
            uint32_t ah2 = AsH[r0 + kw + 4];
            uint32_t ah3 = AsH[r1 + kw + 4];
            uint32_t al0 = AsL[r0 + kw];
            uint32_t al1 = AsL[r1 + kw];
            uint32_t al2 = AsL[r0 + kw + 4];
            uint32_t al3 = AsL[r1 + kw + 4];

            // n-tile 0: cols gw*16 + 0..7
            {
                int cb = (gw * 16 + gq) * BPW;
                uint32_t bh0 = BsH[cb + kw], bh1 = BsH[cb + kw + 4];
                uint32_t bl0 = BsL[cb + kw], bl1 = BsL[cb + kw + 4];
                MMA16816(c0, ah0, ah1, ah2, ah3, bh0, bh1);
                MMA16816(c0, ah0, ah1, ah2, ah3, bl0, bl1);
                MMA16816(c0, al0, al1, al2, al3, bh0, bh1);
            }
            // n-tile 1: cols gw*16 + 8..15
            {
                int cb = (gw * 16 + 8 + gq) * BPW;
                uint32_t bh0 = BsH[cb + kw], bh1 = BsH[cb + kw + 4];
                uint32_t bl0 = BsL[cb + kw], bl1 = BsL[cb + kw + 4];
                MMA16816(c1, ah0, ah1, ah2, ah3, bh0, bh1);
                MMA16816(c1, ah0, ah1, ah2, ah3, bl0, bl1);
                MMA16816(c1, al0, al1, al2, al3, bh0, bh1);
            }
        }
    }

    // --- epilogue: frags -> smem gates ---
    __syncthreads();
    {
        int row = mw * 16 + gq;
        int ch0 = tq * 2;
        smg[gw][row][ch0]         = c0[0];
        smg[gw][row][ch0 + 1]     = c0[1];
        smg[gw][row + 8][ch0]     = c0[2];
        smg[gw][row + 8][ch0 + 1] = c0[3];
        smg[gw][row][ch0 + 8]         = c1[0];
        smg[gw][row][ch0 + 9]         = c1[1];
        smg[gw][row + 8][ch0 + 8]     = c1[2];
        smg[gw][row + 8][ch0 + 9]     = c1[3];
    }
    __syncthreads();

    // --- LSTM cell for 32b x 16h (2 elems per thread) ---
    float* __restrict__ hout = g_h[(t + 1) & 1];
    __nv_bfloat16* __restrict__ houtHi = g_h_hi[(t + 1) & 1];
    __nv_bfloat16* __restrict__ houtLo = g_h_lo[(t + 1) & 1];

#pragma unroll
    for (int e0 = 0; e0 < 2; ++e0) {
        int e  = tid + e0 * 256;          // 0..511
        int b  = e >> 4;
        int hl = e & 15;
        int gb = b0 + b;
        int gh = h0 + hl;
        size_t xb = ((size_t)(t * 4) * B_DIM + gb) * H_DIM + gh;
        const size_t gstride = (size_t)B_DIM * H_DIM;

        float gi = smg[0][b][hl] + g_xg[xb + 0 * gstride] + bias[0 * H_DIM + gh];
        float gf = smg[1][b][hl] + g_xg[xb + 1 * gstride] + bias[1 * H_DIM + gh];
        float go = smg[2][b][hl] + g_xg[xb + 2 * gstride] + bias[2 * H_DIM + gh];
        float gu = smg[3][b][hl] + g_xg[xb + 3 * gstride] + bias[3 * H_DIM + gh];

        float iv = sigmoidf_(gi);
        float fv = sigmoidf_(gf);
        float ov = sigmoidf_(go);
        float uv = tanhf(gu);

        int s = gb * H_DIM + gh;
        float cc = fv * g_c[s] + iv * uv;
        g_c[s] = cc;
        float hv = ov * tanhf(cc);
        hout[s] = hv;
        __nv_bfloat16 hi = __float2bfloat16(hv);
        float lo = hv - __bfloat162float(hi);
        houtHi[s] = hi;
        houtLo[s] = __float2bfloat16(lo);
    }
}

// ---------------------------------------------------------------------------
// copy final h (buffer 0 after 512 steps) to d_out
// ---------------------------------------------------------------------------
__global__ void copy_out_kernel(float* __restrict__ out) {
    int i = blockIdx.x * blockDim.x + threadIdx.x;
    if (i < B_DIM * H_DIM) out[i] = g_h[0][i];
}

// ---------------------------------------------------------------------------
extern "C" void kernel_launch(void* const* d_in, const int* in_sizes, int n_in,
                              void* d_out, int out_size)
{
    const float* x    = (const float*)d_in[0];
    // d_in[1] = adjacency, unused
    const float* Wx   = (const float*)d_in[2];
    const float* Wh   = (const float*)d_in[3];
    const float* bias = (const float*)d_in[4];
    float* out = (float*)d_out;

    init_state_kernel<<<(B_DIM * H_DIM + 255) / 256, 256>>>();
    split_wh_kernel<<<(4 * H_DIM * H_DIM + 255) / 256, 256>>>(Wh);

    // Input-projection GEMM: [65536 x 1024] @ [1024 x 4096] (fp32 SIMT)
    gemm_xgates_kernel<<<dim3(4096 / 128, 65536 / 128), 256>>>(x, Wx);

    // Sequential scan over T with tensor-core steps
    for (int t = 0; t < T_DIM; ++t) {
        lstm_step_mma_kernel<<<dim3(H_DIM / 16, B_DIM / 32), 256>>>(bias, t);
    }

    copy_out_kernel<<<(B_DIM * H_DIM + 255) / 256, 256>>>(out);
}